// round 15
// baseline (speedup 1.0000x reference)
#include <cuda_runtime.h>
#include <cuda_fp16.h>
#include <math.h>
#include <stdint.h>

#define BB   2
#define LL   2048
#define DD   1024
#define HH   16
#define DHD  64
#define HID  4096
#define ROWS (BB*LL)
#define WIN  256
#define DIL  2

// ---------------- scratch (static device globals) ----------------------------
__device__ __half g_xn  [ROWS * DD];
__device__ __half g_qkv [ROWS * 3 * DD];
__device__ __half g_attn[ROWS * DD];
__device__ float  g_y   [ROWS * DD];
__device__ __half g_h   [ROWS * DD];
__device__ __half g_ffn [ROWS * HID];
// transposed weights, [N,K] K-major, half
__device__ __half g_wqkv[3 * DD * DD];
__device__ __half g_wout[DD * DD];
__device__ __half g_w1  [HID * DD];
__device__ __half g_w2  [DD * HID];

// ---------------- helpers -----------------------------------------------------
__device__ __forceinline__ float gelu_exact(float v) {
    return 0.5f * v * (1.0f + erff(v * 0.70710678118654752f));
}
#define CP_ASYNC16(dst, src) \
    asm volatile("cp.async.cg.shared.global [%0], [%1], 16;" :: "r"(dst), "l"(src))
#define CP_COMMIT()  asm volatile("cp.async.commit_group;" ::: "memory")
#define CP_WAIT1()   asm volatile("cp.async.wait_group 1;" ::: "memory")
#define CP_WAIT0()   asm volatile("cp.async.wait_group 0;" ::: "memory")

__device__ __forceinline__ uint32_t smem_u32(const void* p) {
    uint32_t a;
    asm("{ .reg .u64 t; cvta.to.shared.u64 t, %1; cvt.u32.u64 %0, t; }" : "=r"(a) : "l"(p));
    return a;
}
__device__ __forceinline__ void mma_f16(float* c, uint32_t a0, uint32_t a1,
                                        uint32_t a2, uint32_t a3,
                                        uint32_t b0, uint32_t b1) {
    asm volatile(
        "mma.sync.aligned.m16n8k16.row.col.f32.f16.f16.f32 "
        "{%0,%1,%2,%3}, {%4,%5,%6,%7}, {%8,%9}, {%0,%1,%2,%3};"
        : "+f"(c[0]), "+f"(c[1]), "+f"(c[2]), "+f"(c[3])
        : "r"(a0), "r"(a1), "r"(a2), "r"(a3), "r"(b0), "r"(b1));
}
#define LDMX4(r0, r1, r2, r3, addr) \
    asm volatile("ldmatrix.sync.aligned.m8n8.x4.shared.b16 {%0,%1,%2,%3}, [%4];" \
        : "=r"(r0), "=r"(r1), "=r"(r2), "=r"(r3) : "r"(addr))

// ------- prep1: W_qkv transpose (blocks 0..3071) + LN1 (blocks 3072..7167) ---
__global__ __launch_bounds__(256)
void prep1(const float* __restrict__ qkvw, __half* __restrict__ wq,
           const float* __restrict__ x, const float* __restrict__ n1w,
           const float* __restrict__ n1b, __half* __restrict__ xn)
{
    int id = blockIdx.x;
    if (id < 3072) {
        __shared__ float t[32][33];
        int bx = id % 96, by = id / 96;
        int c0 = bx * 32, r0 = by * 32;
        int tx = threadIdx.x & 31, ty = threadIdx.x >> 5;
        const int C = 3 * DD, R = DD;
        #pragma unroll
        for (int i = 0; i < 32; i += 8)
            t[ty + i][tx] = qkvw[(size_t)(r0 + ty + i) * C + c0 + tx];
        __syncthreads();
        #pragma unroll
        for (int i = 0; i < 32; i += 8)
            wq[(size_t)(c0 + ty + i) * R + r0 + tx] = __float2half_rn(t[tx][ty + i]);
    } else {
        int row = id - 3072, tid = threadIdx.x;
        float4 v = reinterpret_cast<const float4*>(x + (size_t)row * DD)[tid];
        float s  = v.x + v.y + v.z + v.w;
        float sq = v.x*v.x + v.y*v.y + v.z*v.z + v.w*v.w;
        __shared__ float sh_s[8], sh_q[8];
        #pragma unroll
        for (int o = 16; o; o >>= 1) {
            s  += __shfl_xor_sync(0xffffffffu, s,  o);
            sq += __shfl_xor_sync(0xffffffffu, sq, o);
        }
        int warp = tid >> 5, lane = tid & 31;
        if (lane == 0) { sh_s[warp] = s; sh_q[warp] = sq; }
        __syncthreads();
        if (warp == 0) {
            s = sh_s[lane & 7]; sq = sh_q[lane & 7];
            #pragma unroll
            for (int o = 4; o; o >>= 1) {
                s  += __shfl_xor_sync(0xffffffffu, s,  o);
                sq += __shfl_xor_sync(0xffffffffu, sq, o);
            }
            if (lane == 0) { sh_s[0] = s; sh_q[0] = sq; }
        }
        __syncthreads();
        float mean = sh_s[0] * (1.0f / DD);
        float var  = sh_q[0] * (1.0f / DD) - mean * mean;
        float rstd = rsqrtf(var + 1e-5f);
        float4 wv = reinterpret_cast<const float4*>(n1w)[tid];
        float4 bv = reinterpret_cast<const float4*>(n1b)[tid];
        __half2 h01 = __floats2half2_rn((v.x - mean) * rstd * wv.x + bv.x,
                                        (v.y - mean) * rstd * wv.y + bv.y);
        __half2 h23 = __floats2half2_rn((v.z - mean) * rstd * wv.z + bv.z,
                                        (v.w - mean) * rstd * wv.w + bv.w);
        __half2* orow = reinterpret_cast<__half2*>(xn + (size_t)row * DD);
        orow[tid * 2]     = h01;
        orow[tid * 2 + 1] = h23;
    }
}

// -------- standalone LayerNorm (LN2) ------------------------------------------
__global__ __launch_bounds__(256)
void ln_kernel(const float* __restrict__ x, const float* __restrict__ w,
               const float* __restrict__ b, __half* __restrict__ out)
{
    int row = blockIdx.x, tid = threadIdx.x;
    float4 v = reinterpret_cast<const float4*>(x + (size_t)row * DD)[tid];
    float s  = v.x + v.y + v.z + v.w;
    float sq = v.x*v.x + v.y*v.y + v.z*v.z + v.w*v.w;
    __shared__ float sh_s[8], sh_q[8];
    #pragma unroll
    for (int o = 16; o; o >>= 1) {
        s  += __shfl_xor_sync(0xffffffffu, s,  o);
        sq += __shfl_xor_sync(0xffffffffu, sq, o);
    }
    int warp = tid >> 5, lane = tid & 31;
    if (lane == 0) { sh_s[warp] = s; sh_q[warp] = sq; }
    __syncthreads();
    if (warp == 0) {
        s = sh_s[lane & 7]; sq = sh_q[lane & 7];
        #pragma unroll
        for (int o = 4; o; o >>= 1) {
            s  += __shfl_xor_sync(0xffffffffu, s,  o);
            sq += __shfl_xor_sync(0xffffffffu, sq, o);
        }
        if (lane == 0) { sh_s[0] = s; sh_q[0] = sq; }
    }
    __syncthreads();
    float mean = sh_s[0] * (1.0f / DD);
    float var  = sh_q[0] * (1.0f / DD) - mean * mean;
    float rstd = rsqrtf(var + 1e-5f);
    float4 wv = reinterpret_cast<const float4*>(w)[tid];
    float4 bv = reinterpret_cast<const float4*>(b)[tid];
    __half2 h01 = __floats2half2_rn((v.x - mean) * rstd * wv.x + bv.x,
                                    (v.y - mean) * rstd * wv.y + bv.y);
    __half2 h23 = __floats2half2_rn((v.z - mean) * rstd * wv.z + bv.z,
                                    (v.w - mean) * rstd * wv.w + bv.w);
    __half2* orow = reinterpret_cast<__half2*>(out + (size_t)row * DD);
    orow[tid * 2]     = h01;
    orow[tid * 2 + 1] = h23;
}

// ------- FP16 tensor GEMM core (device inline) --------------------------------
// CTA 128x128x64, 8 warps (4x2), warp tile 32x64, m16n8k16 + ldmatrix.
#define BKH     64
#define ROWB    144
#define TILEB   (128 * ROWB)
#define STAGEB  (2 * TILEB)
#define NSTG    3
#define GEMM_SMEM (NSTG * STAGEB)      // 110592 B

template<int EPI, typename OutT>
__device__ __forceinline__
void gemm_body(char* smem, const __half* __restrict__ A, const __half* __restrict__ Bt,
               const float* __restrict__ bias, const float* __restrict__ res,
               OutT* __restrict__ C, int N, int K, int bx, int by)
{
    uint32_t sbase = smem_u32(smem);

    int tid = threadIdx.x, lane = tid & 31, wid = tid >> 5;
    int g = lane >> 2, tig = lane & 3;
    int wr0 = (wid & 3) << 5;
    int wc0 = (wid >> 2) << 6;
    int row0 = by << 7, col0 = bx << 7;

    int lm = tid >> 1, lh = tid & 1;
    const __half* ga = A  + (size_t)(row0 + lm) * K + lh * 32;
    const __half* gb = Bt + (size_t)(col0 + lm) * K + lh * 32;
    uint32_t soff = lm * ROWB + lh * 64;

    uint32_t a_off = (uint32_t)(wr0 + (lane & 15)) * ROWB + ((lane >> 4) << 4);
    uint32_t b_off = TILEB + (uint32_t)(wc0 + ((lane >> 4) << 3) + (lane & 7)) * ROWB
                   + (((lane >> 3) & 1) << 4);

    float acc[2][8][4];
    #pragma unroll
    for (int mt = 0; mt < 2; mt++)
        #pragma unroll
        for (int nt = 0; nt < 8; nt++)
            #pragma unroll
            for (int q = 0; q < 4; q++) acc[mt][nt][q] = 0.0f;

    int NC = K >> 6;

    #pragma unroll
    for (int p = 0; p < 2; p++) {
        uint32_t a0 = sbase + p * STAGEB + soff;
        const __half* pa = ga + p * BKH;
        const __half* pb = gb + p * BKH;
        #pragma unroll
        for (int j = 0; j < 4; j++) {
            CP_ASYNC16(a0 + j * 16,         pa + j * 8);
            CP_ASYNC16(a0 + TILEB + j * 16, pb + j * 8);
        }
        CP_COMMIT();
    }

    for (int it = 0; it < NC; it++) {
        CP_WAIT1();
        __syncthreads();

        int nxt = it + 2;
        if (nxt < NC) {
            int st = nxt % NSTG;
            uint32_t a0 = sbase + st * STAGEB + soff;
            const __half* pa = ga + nxt * BKH;
            const __half* pb = gb + nxt * BKH;
            #pragma unroll
            for (int j = 0; j < 4; j++) {
                CP_ASYNC16(a0 + j * 16,         pa + j * 8);
                CP_ASYNC16(a0 + TILEB + j * 16, pb + j * 8);
            }
        }
        CP_COMMIT();

        uint32_t stg = sbase + (uint32_t)(it % NSTG) * STAGEB;
        #pragma unroll
        for (int ks = 0; ks < 4; ks++) {
            uint32_t kb = (uint32_t)ks * 32;
            uint32_t a[2][4];
            #pragma unroll
            for (int mt = 0; mt < 2; mt++) {
                uint32_t addr = stg + a_off + (uint32_t)mt * (16 * ROWB) + kb;
                LDMX4(a[mt][0], a[mt][1], a[mt][2], a[mt][3], addr);
            }
            uint32_t b[8][2];
            #pragma unroll
            for (int ntp = 0; ntp < 4; ntp++) {
                uint32_t addr = stg + b_off + (uint32_t)ntp * (16 * ROWB) + kb;
                LDMX4(b[2*ntp][0], b[2*ntp][1], b[2*ntp+1][0], b[2*ntp+1][1], addr);
            }
            #pragma unroll
            for (int mt = 0; mt < 2; mt++)
                #pragma unroll
                for (int nt = 0; nt < 8; nt++)
                    mma_f16(acc[mt][nt], a[mt][0], a[mt][1], a[mt][2], a[mt][3],
                            b[nt][0], b[nt][1]);
        }
    }

    // epilogue
    #pragma unroll
    for (int mt = 0; mt < 2; mt++) {
        int r1 = row0 + wr0 + mt * 16 + g;
        int r2 = r1 + 8;
        #pragma unroll
        for (int nt = 0; nt < 8; nt++) {
            int col = col0 + wc0 + nt * 8 + tig * 2;
            float2 bv = *reinterpret_cast<const float2*>(bias + col);
            float o0 = acc[mt][nt][0] + bv.x;
            float o1 = acc[mt][nt][1] + bv.y;
            float o2 = acc[mt][nt][2] + bv.x;
            float o3 = acc[mt][nt][3] + bv.y;
            if (EPI == 0) {
                __half2 h1 = __floats2half2_rn(o0, o1);
                __half2 h2 = __floats2half2_rn(o2, o3);
                *reinterpret_cast<__half2*>((__half*)C + (size_t)r1 * N + col) = h1;
                *reinterpret_cast<__half2*>((__half*)C + (size_t)r2 * N + col) = h2;
            } else if (EPI == 1) {
                __half2 h1 = __floats2half2_rn(gelu_exact(o0), gelu_exact(o1));
                __half2 h2 = __floats2half2_rn(gelu_exact(o2), gelu_exact(o3));
                *reinterpret_cast<__half2*>((__half*)C + (size_t)r1 * N + col) = h1;
                *reinterpret_cast<__half2*>((__half*)C + (size_t)r2 * N + col) = h2;
            } else {
                float2 rv1 = *reinterpret_cast<const float2*>(res + (size_t)r1 * N + col);
                float2 rv2 = *reinterpret_cast<const float2*>(res + (size_t)r2 * N + col);
                o0 += rv1.x; o1 += rv1.y; o2 += rv2.x; o3 += rv2.y;
                float2 w1v; w1v.x = o0; w1v.y = o1;
                float2 w2v; w2v.x = o2; w2v.y = o3;
                *reinterpret_cast<float2*>((float*)C + (size_t)r1 * N + col) = w1v;
                *reinterpret_cast<float2*>((float*)C + (size_t)r2 * N + col) = w2v;
            }
        }
    }
}

template<int EPI, typename OutT>
__global__ __launch_bounds__(256, 2)
void tc_gemm(const __half* __restrict__ A, const __half* __restrict__ Bt,
             const float* __restrict__ bias, const float* __restrict__ res,
             OutT* __restrict__ C, int M, int N, int K)
{
    extern __shared__ char smem[];
    gemm_body<EPI, OutT>(smem, A, Bt, bias, res, C, N, K, blockIdx.x, blockIdx.y);
}

// ------- QKV GEMM + fused W_out/W1/W2 transposes ------------------------------
// grid (24+288, 32): x<24 -> GEMM tile; x>=24 -> transpose tile id=(x-24)+288*y.
// Transpose scratch lives in DYNAMIC smem (no static array -> occupancy safe).
__global__ __launch_bounds__(256, 2)
void qkv_gemm_plus(const __half* __restrict__ A, const __half* __restrict__ Bt,
                   const float* __restrict__ bias, __half* __restrict__ C,
                   int N, int K,
                   const float* __restrict__ outw, __half* __restrict__ wo,
                   const float* __restrict__ fw1,  __half* __restrict__ w1,
                   const float* __restrict__ fw2,  __half* __restrict__ w2)
{
    extern __shared__ char smem[];
    if (blockIdx.x >= 24) {
        float* t = reinterpret_cast<float*>(smem);   // [32][33] in dynamic smem
        int id2 = (blockIdx.x - 24) + 288 * blockIdx.y;
        const float* S; __half* T; int R, C2, bx, by;
        if (id2 < 1024)      { S = outw; T = wo; R = DD;  C2 = DD;  bx = id2 & 31;  by = id2 >> 5; }
        else if (id2 < 5120) { int r = id2 - 1024; S = fw1; T = w1; R = DD;  C2 = HID; bx = r & 127; by = r >> 7; }
        else                 { int r = id2 - 5120; S = fw2; T = w2; R = HID; C2 = DD;  bx = r & 31;  by = r >> 5; }
        int c0 = bx * 32, r0 = by * 32;
        int tx = threadIdx.x & 31, ty = threadIdx.x >> 5;
        #pragma unroll
        for (int i = 0; i < 32; i += 8)
            t[(ty + i) * 33 + tx] = S[(size_t)(r0 + ty + i) * C2 + c0 + tx];
        __syncthreads();
        #pragma unroll
        for (int i = 0; i < 32; i += 8)
            T[(size_t)(c0 + ty + i) * R + r0 + tx] = __float2half_rn(t[tx * 33 + ty + i]);
        return;
    }
    gemm_body<0, __half>(smem, A, Bt, bias, nullptr, C, N, K, blockIdx.x, blockIdx.y);
}

// ------- tensor-core dilated attention ----------------------------------------
#define AT_QSTR 72
#define AT_VSTR 202
#define AT_SMEM (64*AT_QSTR*2 + 192*AT_QSTR*2 + 64*AT_VSTR*2)   // 62720 B

__global__ __launch_bounds__(128, 3)
void attn_tc(const __half* __restrict__ qkv, __half* __restrict__ out)
{
    extern __shared__ __half sm[];
    __half* Qs = sm;
    __half* Ks = sm + 64 * AT_QSTR;
    __half* Vt = Ks + 192 * AT_QSTR;
    uint32_t sb = smem_u32(sm);
    uint32_t Qb = sb, Kb = sb + 64 * AT_QSTR * 2;

    int tid = threadIdx.x, lane = tid & 31, w = tid >> 5;
    int bid = blockIdx.x;
    int qa = bid & 15, inst = bid >> 4;
    int p = inst & 1, h = (inst >> 1) & 15, b = inst >> 5;
    int a0 = qa * 64;

    const __half* qbase = qkv + (size_t)b * LL * 3 * DD + h * DHD;

    for (int idx = tid; idx < 512; idx += 128) {
        int row = idx >> 3, ch = idx & 7;
        const __half* src = qbase + (size_t)(p + 2 * (a0 + row)) * 3072 + ch * 8;
        CP_ASYNC16(Qb + (row * AT_QSTR + ch * 8) * 2, src);
    }
    for (int idx = tid; idx < 1536; idx += 128) {
        int row = idx >> 3, ch = idx & 7;
        int c = a0 - 128 + row; if (c < 0) c = 0;
        const __half* src = qbase + (size_t)(p + 2 * c) * 3072 + 1024 + ch * 8;
        CP_ASYNC16(Kb + (row * AT_QSTR + ch * 8) * 2, src);
    }
    CP_COMMIT();
    #pragma unroll
    for (int pass = 0; pass < 12; pass++) {
        int idx = pass * 128 + tid;
        int row = idx >> 3, d0 = (idx & 7) * 8;
        int c = a0 - 128 + row; if (c < 0) c = 0;
        uint4 vv = *reinterpret_cast<const uint4*>(
            qbase + (size_t)(p + 2 * c) * 3072 + 2048 + d0);
        const __half* hv = reinterpret_cast<const __half*>(&vv);
        #pragma unroll
        for (int kk = 0; kk < 8; kk++)
            Vt[(d0 + kk) * AT_VSTR + row] = hv[kk];
    }
    CP_WAIT0();
    __syncthreads();

    int g = lane >> 2, tig = lane & 3;
    int mrow = w * 16 + g;
    const uint32_t* Qw = reinterpret_cast<const uint32_t*>(Qs);
    const uint32_t* Kw = reinterpret_cast<const uint32_t*>(Ks);
    const uint32_t* Vw = reinterpret_cast<const uint32_t*>(Vt);

    uint32_t qf[4][4];
    #pragma unroll
    for (int kb = 0; kb < 4; kb++) {
        int base = mrow * 36 + kb * 8 + tig;
        qf[kb][0] = Qw[base];
        qf[kb][1] = Qw[base + 8 * 36];
        qf[kb][2] = Qw[base + 4];
        qf[kb][3] = Qw[base + 8 * 36 + 4];
    }

    float O[8][4];
    #pragma unroll
    for (int nb = 0; nb < 8; nb++)
        #pragma unroll
        for (int q = 0; q < 4; q++) O[nb][q] = 0.0f;
    float l0 = 0.0f, l1 = 0.0f;
    int ar0 = a0 + mrow, ar1 = ar0 + 8;

    int tstart = (a0 >= 128) ? 0 : (a0 >= 64 ? 1 : 2);

    for (int t = tstart; t < 3; t++) {
        float S[8][4];
        #pragma unroll
        for (int nt = 0; nt < 8; nt++)
            #pragma unroll
            for (int q = 0; q < 4; q++) S[nt][q] = 0.0f;
        #pragma unroll
        for (int kb = 0; kb < 4; kb++) {
            #pragma unroll
            for (int nt = 0; nt < 8; nt++) {
                int nrow = t * 64 + nt * 8 + g;
                int base = nrow * 36 + kb * 8 + tig;
                mma_f16(S[nt], qf[kb][0], qf[kb][1], qf[kb][2], qf[kb][3],
                        Kw[base], Kw[base + 4]);
            }
        }
        uint32_t P[8][2];
        #pragma unroll
        for (int nt = 0; nt < 8; nt++) {
            int c0 = a0 - 128 + t * 64 + nt * 8 + 2 * tig;
            int c1 = c0 + 1;
            float p0 = (c0 >= 0 && c0 <= ar0 && c0 >= ar0 - 128) ? __expf(S[nt][0] * 0.125f) : 0.0f;
            float p1 = (c1 >= 0 && c1 <= ar0 && c1 >= ar0 - 128) ? __expf(S[nt][1] * 0.125f) : 0.0f;
            float p2 = (c0 >= 0 && c0 <= ar1 && c0 >= ar1 - 128) ? __expf(S[nt][2] * 0.125f) : 0.0f;
            float p3 = (c1 >= 0 && c1 <= ar1 && c1 >= ar1 - 128) ? __expf(S[nt][3] * 0.125f) : 0.0f;
            l0 += p0 + p1; l1 += p2 + p3;
            __half2 ha = __floats2half2_rn(p0, p1);
            __half2 hb = __floats2half2_rn(p2, p3);
            P[nt][0] = *reinterpret_cast<uint32_t*>(&ha);
            P[nt][1] = *reinterpret_cast<uint32_t*>(&hb);
        }
        #pragma unroll
        for (int kb2 = 0; kb2 < 4; kb2++) {
            uint32_t pa0 = P[2*kb2][0],   pa1 = P[2*kb2][1];
            uint32_t pa2 = P[2*kb2+1][0], pa3 = P[2*kb2+1][1];
            #pragma unroll
            for (int nb = 0; nb < 8; nb++) {
                int d = nb * 8 + g;
                int base = d * 101 + t * 32 + kb2 * 8 + tig;
                mma_f16(O[nb], pa0, pa1, pa2, pa3, Vw[base], Vw[base + 4]);
            }
        }
    }

    l0 += __shfl_xor_sync(0xffffffffu, l0, 1);
    l0 += __shfl_xor_sync(0xffffffffu, l0, 2);
    l1 += __shfl_xor_sync(0xffffffffu, l1, 1);
    l1 += __shfl_xor_sync(0xffffffffu, l1, 2);
    float i0 = 1.0f / l0, i1 = 1.0f / l1;

    size_t orow0 = (size_t)(b * LL + p + 2 * ar0) * DD;
    size_t orow1 = (size_t)(b * LL + p + 2 * ar1) * DD;
    int colb = h * DHD;
    #pragma unroll
    for (int nb = 0; nb < 8; nb++) {
        int col = colb + nb * 8 + 2 * tig;
        __half2 h0 = __floats2half2_rn(O[nb][0] * i0, O[nb][1] * i0);
        __half2 h1 = __floats2half2_rn(O[nb][2] * i1, O[nb][3] * i1);
        *reinterpret_cast<__half2*>(out + orow0 + col) = h0;
        *reinterpret_cast<__half2*>(out + orow1 + col) = h1;
    }
}

// ---------------- launch ------------------------------------------------------
extern "C" void kernel_launch(void* const* d_in, const int* in_sizes, int n_in,
                              void* d_out, int out_size)
{
    (void)in_sizes; (void)n_in; (void)out_size;
    const float* x    = (const float*)d_in[0];
    const float* n1w  = (const float*)d_in[1];
    const float* n1b  = (const float*)d_in[2];
    const float* qkvw = (const float*)d_in[3];
    const float* qkvb = (const float*)d_in[4];
    const float* outw = (const float*)d_in[5];
    const float* outb = (const float*)d_in[6];
    const float* n2w  = (const float*)d_in[7];
    const float* n2b  = (const float*)d_in[8];
    const float* fw1  = (const float*)d_in[9];
    const float* fb1  = (const float*)d_in[10];
    const float* fw2  = (const float*)d_in[11];
    const float* fb2  = (const float*)d_in[12];
    float* out = (float*)d_out;

    __half *xn, *qkv, *attn, *hbuf, *ffn, *wq, *wo, *w1, *w2;
    float *y;
    cudaGetSymbolAddress((void**)&xn,   g_xn);
    cudaGetSymbolAddress((void**)&qkv,  g_qkv);
    cudaGetSymbolAddress((void**)&attn, g_attn);
    cudaGetSymbolAddress((void**)&y,    g_y);
    cudaGetSymbolAddress((void**)&hbuf, g_h);
    cudaGetSymbolAddress((void**)&ffn,  g_ffn);
    cudaGetSymbolAddress((void**)&wq,   g_wqkv);
    cudaGetSymbolAddress((void**)&wo,   g_wout);
    cudaGetSymbolAddress((void**)&w1,   g_w1);
    cudaGetSymbolAddress((void**)&w2,   g_w2);

    cudaFuncSetAttribute(qkv_gemm_plus,          cudaFuncAttributeMaxDynamicSharedMemorySize, GEMM_SMEM);
    cudaFuncSetAttribute(tc_gemm<1, __half>,     cudaFuncAttributeMaxDynamicSharedMemorySize, GEMM_SMEM);
    cudaFuncSetAttribute(tc_gemm<2, float>,      cudaFuncAttributeMaxDynamicSharedMemorySize, GEMM_SMEM);
    cudaFuncSetAttribute(attn_tc,                cudaFuncAttributeMaxDynamicSharedMemorySize, AT_SMEM);

    // 1. W_qkv transpose + LN1 (fused, independent halves)
    prep1<<<3072 + ROWS, 256>>>(qkvw, wq, x, n1w, n1b, xn);
    // 2. QKV GEMM + W_out/W1/W2 transposes (fused into one launch)
    qkv_gemm_plus<<<dim3(24 + 288, ROWS / 128), 256, GEMM_SMEM>>>(
        xn, wq, qkvb, qkv, 3 * DD, DD, outw, wo, fw1, w1, fw2, w2);
    // 3. attention (tensor-core)
    attn_tc<<<1024, 128, AT_SMEM>>>(qkv, attn);
    // 4. y = attn @ out_w + out_b + x -> fp32
    tc_gemm<2, float><<<dim3(DD / 128, ROWS / 128), 256, GEMM_SMEM>>>(
        attn, wo, outb, x, y, ROWS, DD, DD);
    // 5. LN2 -> half
    ln_kernel<<<ROWS, 256>>>(y, n2w, n2b, hbuf);
    // 6. ffn = gelu(h @ w1 + b1) -> half
    tc_gemm<1, __half><<<dim3(HID / 128, ROWS / 128), 256, GEMM_SMEM>>>(
        hbuf, w1, fb1, nullptr, ffn, ROWS, HID, DD);
    // 7. out = ffn @ w2 + b2 + y -> fp32
    tc_gemm<2, float><<<dim3(DD / 128, ROWS / 128), 256, GEMM_SMEM>>>(
        ffn, w2, fb2, y, out, ROWS, DD, HID);
}

// round 17
// speedup vs baseline: 1.1439x; 1.1439x over previous
#include <cuda_runtime.h>
#include <cuda_fp16.h>
#include <math.h>
#include <stdint.h>

#define BB   2
#define LL   2048
#define DD   1024
#define HH   16
#define DHD  64
#define HID  4096
#define ROWS (BB*LL)
#define WIN  256
#define DIL  2

// ---------------- scratch (static device globals) ----------------------------
__device__ __half g_xn  [ROWS * DD];
__device__ __half g_qkv [ROWS * 3 * DD];
__device__ __half g_attn[ROWS * DD];
__device__ float  g_y   [ROWS * DD];
__device__ __half g_h   [ROWS * DD];
__device__ __half g_ffn [ROWS * HID];
// transposed weights, [N,K] K-major, half
__device__ __half g_wqkv[3 * DD * DD];
__device__ __half g_wout[DD * DD];
__device__ __half g_w1  [HID * DD];
__device__ __half g_w2  [DD * HID];

// ---------------- helpers -----------------------------------------------------
__device__ __forceinline__ float gelu_exact(float v) {
    return 0.5f * v * (1.0f + erff(v * 0.70710678118654752f));
}
#define CP_ASYNC16(dst, src) \
    asm volatile("cp.async.cg.shared.global [%0], [%1], 16;" :: "r"(dst), "l"(src))
#define CP_COMMIT()  asm volatile("cp.async.commit_group;" ::: "memory")
#define CP_WAIT3()   asm volatile("cp.async.wait_group 3;" ::: "memory")
#define CP_WAIT0()   asm volatile("cp.async.wait_group 0;" ::: "memory")

__device__ __forceinline__ uint32_t smem_u32(const void* p) {
    uint32_t a;
    asm("{ .reg .u64 t; cvta.to.shared.u64 t, %1; cvt.u32.u64 %0, t; }" : "=r"(a) : "l"(p));
    return a;
}
__device__ __forceinline__ void mma_f16(float* c, uint32_t a0, uint32_t a1,
                                        uint32_t a2, uint32_t a3,
                                        uint32_t b0, uint32_t b1) {
    asm volatile(
        "mma.sync.aligned.m16n8k16.row.col.f32.f16.f16.f32 "
        "{%0,%1,%2,%3}, {%4,%5,%6,%7}, {%8,%9}, {%0,%1,%2,%3};"
        : "+f"(c[0]), "+f"(c[1]), "+f"(c[2]), "+f"(c[3])
        : "r"(a0), "r"(a1), "r"(a2), "r"(a3), "r"(b0), "r"(b1));
}
#define LDMX4(r0, r1, r2, r3, addr) \
    asm volatile("ldmatrix.sync.aligned.m8n8.x4.shared.b16 {%0,%1,%2,%3}, [%4];" \
        : "=r"(r0), "=r"(r1), "=r"(r2), "=r"(r3) : "r"(addr))

// ------- merged transposes: 4 weight tensors, fp32 [R][C] -> half [C][R] -----
__global__ __launch_bounds__(256)
void transpose_all(const float* __restrict__ s0, __half* __restrict__ t0,
                   const float* __restrict__ s1, __half* __restrict__ t1,
                   const float* __restrict__ s2, __half* __restrict__ t2,
                   const float* __restrict__ s3, __half* __restrict__ t3)
{
    __shared__ float t[32][33];
    int id = blockIdx.x;
    const float* S; __half* T; int R, C, bx, by;
    if (id < 3072)      { int r = id;        S=s0; T=t0; R=DD;  C=3*DD; bx=r%96;  by=r/96;  }
    else if (id < 4096) { int r = id - 3072; S=s1; T=t1; R=DD;  C=DD;   bx=r%32;  by=r/32;  }
    else if (id < 8192) { int r = id - 4096; S=s2; T=t2; R=DD;  C=HID;  bx=r%128; by=r/128; }
    else                { int r = id - 8192; S=s3; T=t3; R=HID; C=DD;   bx=r%32;  by=r/32;  }
    int c0 = bx * 32, r0 = by * 32;
    int tx = threadIdx.x & 31, ty = threadIdx.x >> 5;
    #pragma unroll
    for (int i = 0; i < 32; i += 8)
        t[ty + i][tx] = S[(size_t)(r0 + ty + i) * C + c0 + tx];
    __syncthreads();
    #pragma unroll
    for (int i = 0; i < 32; i += 8)
        T[(size_t)(c0 + ty + i) * R + r0 + tx] = __float2half_rn(t[tx][ty + i]);
}

// -------- LayerNorm: fp32 in -> half out --------------------------------------
__global__ __launch_bounds__(256)
void ln_kernel(const float* __restrict__ x, const float* __restrict__ w,
               const float* __restrict__ b, __half* __restrict__ out)
{
    int row = blockIdx.x, tid = threadIdx.x;
    float4 v = reinterpret_cast<const float4*>(x + (size_t)row * DD)[tid];
    float s  = v.x + v.y + v.z + v.w;
    float sq = v.x*v.x + v.y*v.y + v.z*v.z + v.w*v.w;
    __shared__ float sh_s[8], sh_q[8];
    #pragma unroll
    for (int o = 16; o; o >>= 1) {
        s  += __shfl_xor_sync(0xffffffffu, s,  o);
        sq += __shfl_xor_sync(0xffffffffu, sq, o);
    }
    int warp = tid >> 5, lane = tid & 31;
    if (lane == 0) { sh_s[warp] = s; sh_q[warp] = sq; }
    __syncthreads();
    if (warp == 0) {
        s = sh_s[lane & 7]; sq = sh_q[lane & 7];
        #pragma unroll
        for (int o = 4; o; o >>= 1) {
            s  += __shfl_xor_sync(0xffffffffu, s,  o);
            sq += __shfl_xor_sync(0xffffffffu, sq, o);
        }
        if (lane == 0) { sh_s[0] = s; sh_q[0] = sq; }
    }
    __syncthreads();
    float mean = sh_s[0] * (1.0f / DD);
    float var  = sh_q[0] * (1.0f / DD) - mean * mean;
    float rstd = rsqrtf(var + 1e-5f);
    float4 wv = reinterpret_cast<const float4*>(w)[tid];
    float4 bv = reinterpret_cast<const float4*>(b)[tid];
    __half2 h01 = __floats2half2_rn((v.x - mean) * rstd * wv.x + bv.x,
                                    (v.y - mean) * rstd * wv.y + bv.y);
    __half2 h23 = __floats2half2_rn((v.z - mean) * rstd * wv.z + bv.z,
                                    (v.w - mean) * rstd * wv.w + bv.w);
    __half2* orow = reinterpret_cast<__half2*>(out + (size_t)row * DD);
    orow[tid * 2]     = h01;
    orow[tid * 2 + 1] = h23;
}

// ------- FP16 tensor GEMM: C = A[M,K] @ Bt[N,K]^T + epilogue -----------------
// CTA 128x128, 8 warps (4x2), warp tile 32x64, m16n8k16 + ldmatrix.
// 5 stages x K=32 halves (row stride 80B, 16-aligned), lookahead 4, wait 3.
#define BKH     32                     // K halves per stage
#define ROWB    80                     // bytes per smem row (64B data + 16B pad)
#define TILEB   (128 * ROWB)           // 10240 B per operand
#define STAGEB  (2 * TILEB)            // 20480 B
#define NSTG    5
#define GEMM_SMEM (NSTG * STAGEB)      // 102400 B (2 CTAs = 200 KB <= 228 KB)

template<int EPI, typename OutT>
__global__ __launch_bounds__(256, 2)
void tc_gemm(const __half* __restrict__ A, const __half* __restrict__ Bt,
             const float* __restrict__ bias, const float* __restrict__ res,
             OutT* __restrict__ C, int M, int N, int K)
{
    extern __shared__ char smem[];
    uint32_t sbase = smem_u32(smem);

    int tid = threadIdx.x, lane = tid & 31, wid = tid >> 5;
    int g = lane >> 2, tig = lane & 3;
    int wr0 = (wid & 3) << 5;
    int wc0 = (wid >> 2) << 6;
    int row0 = blockIdx.y << 7, col0 = blockIdx.x << 7;

    int lm = tid >> 1, lh = tid & 1;
    const __half* ga = A  + (size_t)(row0 + lm) * K + lh * 16;
    const __half* gb = Bt + (size_t)(col0 + lm) * K + lh * 16;
    uint32_t soff = lm * ROWB + lh * 32;

    uint32_t a_off = (uint32_t)(wr0 + (lane & 15)) * ROWB + ((lane >> 4) << 4);
    uint32_t b_off = TILEB + (uint32_t)(wc0 + ((lane >> 4) << 3) + (lane & 7)) * ROWB
                   + (((lane >> 3) & 1) << 4);

    float acc[2][8][4];
    #pragma unroll
    for (int mt = 0; mt < 2; mt++)
        #pragma unroll
        for (int nt = 0; nt < 8; nt++)
            #pragma unroll
            for (int q = 0; q < 4; q++) acc[mt][nt][q] = 0.0f;

    int NC = K >> 5;          // K=32-half stages

    #pragma unroll
    for (int p = 0; p < 4; p++) {
        uint32_t a0 = sbase + p * STAGEB + soff;
        const __half* pa = ga + p * BKH;
        const __half* pb = gb + p * BKH;
        #pragma unroll
        for (int j = 0; j < 2; j++) {
            CP_ASYNC16(a0 + j * 16,         pa + j * 8);
            CP_ASYNC16(a0 + TILEB + j * 16, pb + j * 8);
        }
        CP_COMMIT();
    }

    for (int it = 0; it < NC; it++) {
        CP_WAIT3();
        __syncthreads();

        int nxt = it + 4;
        if (nxt < NC) {
            int st = nxt % NSTG;
            uint32_t a0 = sbase + st * STAGEB + soff;
            const __half* pa = ga + nxt * BKH;
            const __half* pb = gb + nxt * BKH;
            #pragma unroll
            for (int j = 0; j < 2; j++) {
                CP_ASYNC16(a0 + j * 16,         pa + j * 8);
                CP_ASYNC16(a0 + TILEB + j * 16, pb + j * 8);
            }
        }
        CP_COMMIT();

        uint32_t stg = sbase + (uint32_t)(it % NSTG) * STAGEB;
        #pragma unroll
        for (int ks = 0; ks < 2; ks++) {
            uint32_t kb = (uint32_t)ks * 32;
            uint32_t a[2][4];
            #pragma unroll
            for (int mt = 0; mt < 2; mt++) {
                uint32_t addr = stg + a_off + (uint32_t)mt * (16 * ROWB) + kb;
                LDMX4(a[mt][0], a[mt][1], a[mt][2], a[mt][3], addr);
            }
            uint32_t b[8][2];
            #pragma unroll
            for (int ntp = 0; ntp < 4; ntp++) {
                uint32_t addr = stg + b_off + (uint32_t)ntp * (16 * ROWB) + kb;
                LDMX4(b[2*ntp][0], b[2*ntp][1], b[2*ntp+1][0], b[2*ntp+1][1], addr);
            }
            #pragma unroll
            for (int mt = 0; mt < 2; mt++)
                #pragma unroll
                for (int nt = 0; nt < 8; nt++)
                    mma_f16(acc[mt][nt], a[mt][0], a[mt][1], a[mt][2], a[mt][3],
                            b[nt][0], b[nt][1]);
        }
    }

    // epilogue
    #pragma unroll
    for (int mt = 0; mt < 2; mt++) {
        int r1 = row0 + wr0 + mt * 16 + g;
        int r2 = r1 + 8;
        #pragma unroll
        for (int nt = 0; nt < 8; nt++) {
            int col = col0 + wc0 + nt * 8 + tig * 2;
            float2 bv = *reinterpret_cast<const float2*>(bias + col);
            float o0 = acc[mt][nt][0] + bv.x;
            float o1 = acc[mt][nt][1] + bv.y;
            float o2 = acc[mt][nt][2] + bv.x;
            float o3 = acc[mt][nt][3] + bv.y;
            if (EPI == 0) {
                __half2 h1 = __floats2half2_rn(o0, o1);
                __half2 h2 = __floats2half2_rn(o2, o3);
                *reinterpret_cast<__half2*>((__half*)C + (size_t)r1 * N + col) = h1;
                *reinterpret_cast<__half2*>((__half*)C + (size_t)r2 * N + col) = h2;
            } else if (EPI == 1) {
                __half2 h1 = __floats2half2_rn(gelu_exact(o0), gelu_exact(o1));
                __half2 h2 = __floats2half2_rn(gelu_exact(o2), gelu_exact(o3));
                *reinterpret_cast<__half2*>((__half*)C + (size_t)r1 * N + col) = h1;
                *reinterpret_cast<__half2*>((__half*)C + (size_t)r2 * N + col) = h2;
            } else {
                float2 rv1 = *reinterpret_cast<const float2*>(res + (size_t)r1 * N + col);
                float2 rv2 = *reinterpret_cast<const float2*>(res + (size_t)r2 * N + col);
                o0 += rv1.x; o1 += rv1.y; o2 += rv2.x; o3 += rv2.y;
                float2 w1v; w1v.x = o0; w1v.y = o1;
                float2 w2v; w2v.x = o2; w2v.y = o3;
                *reinterpret_cast<float2*>((float*)C + (size_t)r1 * N + col) = w1v;
                *reinterpret_cast<float2*>((float*)C + (size_t)r2 * N + col) = w2v;
            }
        }
    }
}

// ------- tensor-core dilated attention ----------------------------------------
#define AT_QSTR 72
#define AT_VSTR 202
#define AT_SMEM (64*AT_QSTR*2 + 192*AT_QSTR*2 + 64*AT_VSTR*2)   // 62720 B

__global__ __launch_bounds__(128, 3)
void attn_tc(const __half* __restrict__ qkv, __half* __restrict__ out)
{
    extern __shared__ __half sm[];
    __half* Qs = sm;
    __half* Ks = sm + 64 * AT_QSTR;
    __half* Vt = Ks + 192 * AT_QSTR;
    uint32_t sb = smem_u32(sm);
    uint32_t Qb = sb, Kb = sb + 64 * AT_QSTR * 2;

    int tid = threadIdx.x, lane = tid & 31, w = tid >> 5;
    int bid = blockIdx.x;
    int qa = bid & 15, inst = bid >> 4;
    int p = inst & 1, h = (inst >> 1) & 15, b = inst >> 5;
    int a0 = qa * 64;

    const __half* qbase = qkv + (size_t)b * LL * 3 * DD + h * DHD;

    for (int idx = tid; idx < 512; idx += 128) {
        int row = idx >> 3, ch = idx & 7;
        const __half* src = qbase + (size_t)(p + 2 * (a0 + row)) * 3072 + ch * 8;
        CP_ASYNC16(Qb + (row * AT_QSTR + ch * 8) * 2, src);
    }
    for (int idx = tid; idx < 1536; idx += 128) {
        int row = idx >> 3, ch = idx & 7;
        int c = a0 - 128 + row; if (c < 0) c = 0;
        const __half* src = qbase + (size_t)(p + 2 * c) * 3072 + 1024 + ch * 8;
        CP_ASYNC16(Kb + (row * AT_QSTR + ch * 8) * 2, src);
    }
    CP_COMMIT();
    #pragma unroll
    for (int pass = 0; pass < 12; pass++) {
        int idx = pass * 128 + tid;
        int row = idx >> 3, d0 = (idx & 7) * 8;
        int c = a0 - 128 + row; if (c < 0) c = 0;
        uint4 vv = *reinterpret_cast<const uint4*>(
            qbase + (size_t)(p + 2 * c) * 3072 + 2048 + d0);
        const __half* hv = reinterpret_cast<const __half*>(&vv);
        #pragma unroll
        for (int kk = 0; kk < 8; kk++)
            Vt[(d0 + kk) * AT_VSTR + row] = hv[kk];
    }
    CP_WAIT0();
    __syncthreads();

    int g = lane >> 2, tig = lane & 3;
    int mrow = w * 16 + g;
    const uint32_t* Qw = reinterpret_cast<const uint32_t*>(Qs);
    const uint32_t* Kw = reinterpret_cast<const uint32_t*>(Ks);
    const uint32_t* Vw = reinterpret_cast<const uint32_t*>(Vt);

    uint32_t qf[4][4];
    #pragma unroll
    for (int kb = 0; kb < 4; kb++) {
        int base = mrow * 36 + kb * 8 + tig;
        qf[kb][0] = Qw[base];
        qf[kb][1] = Qw[base + 8 * 36];
        qf[kb][2] = Qw[base + 4];
        qf[kb][3] = Qw[base + 8 * 36 + 4];
    }

    float O[8][4];
    #pragma unroll
    for (int nb = 0; nb < 8; nb++)
        #pragma unroll
        for (int q = 0; q < 4; q++) O[nb][q] = 0.0f;
    float l0 = 0.0f, l1 = 0.0f;
    int ar0 = a0 + mrow, ar1 = ar0 + 8;

    int tstart = (a0 >= 128) ? 0 : (a0 >= 64 ? 1 : 2);

    for (int t = tstart; t < 3; t++) {
        float S[8][4];
        #pragma unroll
        for (int nt = 0; nt < 8; nt++)
            #pragma unroll
            for (int q = 0; q < 4; q++) S[nt][q] = 0.0f;
        #pragma unroll
        for (int kb = 0; kb < 4; kb++) {
            #pragma unroll
            for (int nt = 0; nt < 8; nt++) {
                int nrow = t * 64 + nt * 8 + g;
                int base = nrow * 36 + kb * 8 + tig;
                mma_f16(S[nt], qf[kb][0], qf[kb][1], qf[kb][2], qf[kb][3],
                        Kw[base], Kw[base + 4]);
            }
        }
        uint32_t P[8][2];
        #pragma unroll
        for (int nt = 0; nt < 8; nt++) {
            int c0 = a0 - 128 + t * 64 + nt * 8 + 2 * tig;
            int c1 = c0 + 1;
            float p0 = (c0 >= 0 && c0 <= ar0 && c0 >= ar0 - 128) ? __expf(S[nt][0] * 0.125f) : 0.0f;
            float p1 = (c1 >= 0 && c1 <= ar0 && c1 >= ar0 - 128) ? __expf(S[nt][1] * 0.125f) : 0.0f;
            float p2 = (c0 >= 0 && c0 <= ar1 && c0 >= ar1 - 128) ? __expf(S[nt][2] * 0.125f) : 0.0f;
            float p3 = (c1 >= 0 && c1 <= ar1 && c1 >= ar1 - 128) ? __expf(S[nt][3] * 0.125f) : 0.0f;
            l0 += p0 + p1; l1 += p2 + p3;
            __half2 ha = __floats2half2_rn(p0, p1);
            __half2 hb = __floats2half2_rn(p2, p3);
            P[nt][0] = *reinterpret_cast<uint32_t*>(&ha);
            P[nt][1] = *reinterpret_cast<uint32_t*>(&hb);
        }
        #pragma unroll
        for (int kb2 = 0; kb2 < 4; kb2++) {
            uint32_t pa0 = P[2*kb2][0],   pa1 = P[2*kb2][1];
            uint32_t pa2 = P[2*kb2+1][0], pa3 = P[2*kb2+1][1];
            #pragma unroll
            for (int nb = 0; nb < 8; nb++) {
                int d = nb * 8 + g;
                int base = d * 101 + t * 32 + kb2 * 8 + tig;
                mma_f16(O[nb], pa0, pa1, pa2, pa3, Vw[base], Vw[base + 4]);
            }
        }
    }

    l0 += __shfl_xor_sync(0xffffffffu, l0, 1);
    l0 += __shfl_xor_sync(0xffffffffu, l0, 2);
    l1 += __shfl_xor_sync(0xffffffffu, l1, 1);
    l1 += __shfl_xor_sync(0xffffffffu, l1, 2);
    float i0 = 1.0f / l0, i1 = 1.0f / l1;

    size_t orow0 = (size_t)(b * LL + p + 2 * ar0) * DD;
    size_t orow1 = (size_t)(b * LL + p + 2 * ar1) * DD;
    int colb = h * DHD;
    #pragma unroll
    for (int nb = 0; nb < 8; nb++) {
        int col = colb + nb * 8 + 2 * tig;
        __half2 h0 = __floats2half2_rn(O[nb][0] * i0, O[nb][1] * i0);
        __half2 h1 = __floats2half2_rn(O[nb][2] * i1, O[nb][3] * i1);
        *reinterpret_cast<__half2*>(out + orow0 + col) = h0;
        *reinterpret_cast<__half2*>(out + orow1 + col) = h1;
    }
}

// ---------------- launch ------------------------------------------------------
extern "C" void kernel_launch(void* const* d_in, const int* in_sizes, int n_in,
                              void* d_out, int out_size)
{
    (void)in_sizes; (void)n_in; (void)out_size;
    const float* x    = (const float*)d_in[0];
    const float* n1w  = (const float*)d_in[1];
    const float* n1b  = (const float*)d_in[2];
    const float* qkvw = (const float*)d_in[3];
    const float* qkvb = (const float*)d_in[4];
    const float* outw = (const float*)d_in[5];
    const float* outb = (const float*)d_in[6];
    const float* n2w  = (const float*)d_in[7];
    const float* n2b  = (const float*)d_in[8];
    const float* fw1  = (const float*)d_in[9];
    const float* fb1  = (const float*)d_in[10];
    const float* fw2  = (const float*)d_in[11];
    const float* fb2  = (const float*)d_in[12];
    float* out = (float*)d_out;

    __half *xn, *qkv, *attn, *hbuf, *ffn, *wq, *wo, *w1, *w2;
    float *y;
    cudaGetSymbolAddress((void**)&xn,   g_xn);
    cudaGetSymbolAddress((void**)&qkv,  g_qkv);
    cudaGetSymbolAddress((void**)&attn, g_attn);
    cudaGetSymbolAddress((void**)&y,    g_y);
    cudaGetSymbolAddress((void**)&hbuf, g_h);
    cudaGetSymbolAddress((void**)&ffn,  g_ffn);
    cudaGetSymbolAddress((void**)&wq,   g_wqkv);
    cudaGetSymbolAddress((void**)&wo,   g_wout);
    cudaGetSymbolAddress((void**)&w1,   g_w1);
    cudaGetSymbolAddress((void**)&w2,   g_w2);

    cudaFuncSetAttribute(tc_gemm<0, __half>, cudaFuncAttributeMaxDynamicSharedMemorySize, GEMM_SMEM);
    cudaFuncSetAttribute(tc_gemm<1, __half>, cudaFuncAttributeMaxDynamicSharedMemorySize, GEMM_SMEM);
    cudaFuncSetAttribute(tc_gemm<2, float>,  cudaFuncAttributeMaxDynamicSharedMemorySize, GEMM_SMEM);
    cudaFuncSetAttribute(attn_tc,            cudaFuncAttributeMaxDynamicSharedMemorySize, AT_SMEM);

    transpose_all<<<12288, 256>>>(qkvw, wq, outw, wo, fw1, w1, fw2, w2);

    // 1. LN1 -> half
    ln_kernel<<<ROWS, 256>>>(x, n1w, n1b, xn);
    // 2. QKV -> half
    tc_gemm<0, __half><<<dim3(3 * DD / 128, ROWS / 128), 256, GEMM_SMEM>>>(
        xn, wq, qkvb, nullptr, qkv, ROWS, 3 * DD, DD);
    // 3. attention (tensor-core)
    attn_tc<<<1024, 128, AT_SMEM>>>(qkv, attn);
    // 4. y = attn @ out_w + out_b + x -> fp32
    tc_gemm<2, float><<<dim3(DD / 128, ROWS / 128), 256, GEMM_SMEM>>>(
        attn, wo, outb, x, y, ROWS, DD, DD);
    // 5. LN2 -> half
    ln_kernel<<<ROWS, 256>>>(y, n2w, n2b, hbuf);
    // 6. ffn = gelu(h @ w1 + b1) -> half
    tc_gemm<1, __half><<<dim3(HID / 128, ROWS / 128), 256, GEMM_SMEM>>>(
        hbuf, w1, fb1, nullptr, ffn, ROWS, HID, DD);
    // 7. out = ffn @ w2 + b2 + y -> fp32
    tc_gemm<2, float><<<dim3(DD / 128, ROWS / 128), 256, GEMM_SMEM>>>(
        ffn, w2, fb2, y, out, ROWS, DD, HID);
}